// round 4
// baseline (speedup 1.0000x reference)
#include <cuda_runtime.h>

// NoTradeRegionRNN: D=2 channel RNN scan, T timesteps, B independent lanes.
// x, returns: (D, T, B) row-major. output: (D, T, B) then hT (D, 1, B).
//
// R4: two independent batch lanes per thread (ILP=2) so the two serial
// recurrence chains interleave and hide each other's FFMA/MUFU/memory
// latency (a single warp per SMSP has nothing else to hide behind).
// Adjacent lanes -> all global traffic is float2 (LDG.64 / STG.64).
// Compile-time T,B so all in-group offsets are immediates; PF=8 step-pair
// software prefetch (32 LDG.64 in flight per warp).

__device__ __forceinline__ float relu_(float v) { return fmaxf(v, 0.0f); }
__device__ __forceinline__ float clamp_(float v, float lo, float hi) {
    return fminf(fmaxf(v, lo), hi);
}
__device__ __forceinline__ float frcp_(float v) {
    float r;
    asm("rcp.approx.f32 %0, %1;" : "=f"(r) : "f"(v));
    return r;
}

// ---------------- shared parameter block ----------------
struct Params {
    float ac, bd;
    float Wi0, Wi1, Wh0, Wh1, W10, W11, W20, W21;
    // clamp-form bound constants: val = clamp(fma(a, slope, C), LO, HI)
    float C_lbx, LO_lbx, HI_lbx;
    float C_ubx, LO_ubx, HI_ubx;
    float C_lby, LO_lby, HI_lby;
    float C_uby, LO_uby, HI_uby;
};

__device__ __forceinline__ Params make_params(
    const float* __restrict__ tgt, const float* __restrict__ wi,
    const float* __restrict__ wh,  const float* __restrict__ bh,
    const float* __restrict__ w1,  const float* __restrict__ w2,
    const float* __restrict__ wr)
{
    Params P;
    const float wr00 = wr[0], wr01 = wr[1], wr10 = wr[2], wr11 = wr[3];
    const float bh0 = bh[0], bh1 = bh[1];
    const float t0 = tgt[0], t1 = tgt[1];
    P.Wi0 = wi[0]; P.Wi1 = wi[1];
    P.Wh0 = wh[0]; P.Wh1 = wh[1];
    P.W10 = w1[0]; P.W11 = w1[1];
    P.W20 = w2[0]; P.W21 = w2[1];
    P.ac = wr10 / wr00;
    P.bd = wr01 / wr11;

    // Corners: k0:(-,-) k1:(-,+) k2:(+,+) k3:(+,-) applied to (bh0, bh1)
    float Cx[4], Cy[4];
    const float s0[4] = {-1.f, -1.f, 1.f, 1.f};
    const float s1[4] = {-1.f,  1.f, 1.f, -1.f};
#pragma unroll
    for (int k = 0; k < 4; ++k) {
        float vx = s0[k] * bh0, vy = s1[k] * bh1;
        Cx[k] = wr00 * vx + wr01 * vy + t0;
        Cy[k] = wr10 * vx + wr11 * vy + t1;
    }
    const bool bdp = (P.bd >= 0.0f);
    const bool acp = (P.ac >= 0.0f);

    // bound: w = (a - c)*slope ; val = o - relu(A - relu(w))
    //        == clamp(w + o - A, o - A, o)
    {
        float c = bdp ? Cy[0] : Cy[1], A = fabsf(Cx[1] - Cx[0]), o = bdp ? Cx[1] : Cx[0];
        P.C_lbx = -c * P.bd + o - A; P.LO_lbx = o - A; P.HI_lbx = o;
    }
    {
        float c = bdp ? Cy[3] : Cy[2], A = fabsf(Cx[2] - Cx[3]), o = bdp ? Cx[2] : Cx[3];
        P.C_ubx = -c * P.bd + o - A; P.LO_ubx = o - A; P.HI_ubx = o;
    }
    {
        float c = acp ? Cx[0] : Cx[3], A = fabsf(Cy[0] - Cy[3]), o = acp ? Cy[3] : Cy[0];
        P.C_lby = -c * P.ac + o - A; P.LO_lby = o - A; P.HI_lby = o;
    }
    {
        float c = acp ? Cx[1] : Cx[2], A = fabsf(Cy[1] - Cy[2]), o = acp ? Cy[2] : Cy[1];
        P.C_uby = -c * P.ac + o - A; P.LO_uby = o - A; P.HI_uby = o;
    }
    return P;
}

// one recurrence step for one lane
__device__ __forceinline__ void ntr_step(const Params& P,
                                         float& hx, float& hy,
                                         float rx, float ry,
                                         float xx, float xy)
{
    float denom = fmaf(hx, rx, fmaf(hy, ry, 1.0f));
    float inv = frcp_(denom);
    float ax = (hx * (1.0f + rx)) * inv;
    float ay = (hy * (1.0f + ry)) * inv;

    float lbx = clamp_(fmaf(ay, P.bd, P.C_lbx), P.LO_lbx, P.HI_lbx);
    float ubx = clamp_(fmaf(ay, P.bd, P.C_ubx), P.LO_ubx, P.HI_ubx);
    float lby = clamp_(fmaf(ax, P.ac, P.C_lby), P.LO_lby, P.HI_lby);
    float uby = clamp_(fmaf(ax, P.ac, P.C_uby), P.LO_uby, P.HI_uby);

    float g1x = relu_(fmaf(P.Wi0, xx, fmaf(P.Wh0, ax, -lbx)));
    float g1y = relu_(fmaf(P.Wi1, xy, fmaf(P.Wh1, ay, -lby)));
    float g2x = relu_(fmaf(P.W10, g1x, ubx - lbx));
    float g2y = relu_(fmaf(P.W11, g1y, uby - lby));
    hx = fmaf(P.W20, g2x, ubx);
    hy = fmaf(P.W21, g2y, uby);
}

// both lanes of a float2-pair
__device__ __forceinline__ void ntr_step2(const Params& P,
                                          float2& hx, float2& hy,
                                          float2 r0, float2 r1,
                                          float2 x0, float2 x1)
{
    ntr_step(P, hx.x, hy.x, r0.x, r1.x, x0.x, x1.x);
    ntr_step(P, hx.y, hy.y, r0.y, r1.y, x0.y, x1.y);
}

// ---------------- specialized ILP2 kernel: compile-time T, B ----------------
template <int T, int B, int PF>
__global__ void __launch_bounds__(64)
ntr_rnn_ilp2(const float* __restrict__ x,
             const float* __restrict__ ret,
             const float* __restrict__ tgt,
             const float* __restrict__ wi,
             const float* __restrict__ wh,
             const float* __restrict__ bh,
             const float* __restrict__ w1,
             const float* __restrict__ w2,
             const float* __restrict__ wr,
             float* __restrict__ out,
             int write_hT)
{
    const int tid = blockIdx.x * blockDim.x + threadIdx.x;   // lane-pair id
    const Params P = make_params(tgt, wi, wh, bh, w1, w2, wr);

    constexpr int STEPS = T - 1;
    constexpr int MAIN_END = ((STEPS - PF) / PF) * PF;
    constexpr int REM_AFTER_A = STEPS - MAIN_END - PF;
    constexpr int B2 = B / 2;               // float2 stride per timestep
    constexpr size_t TB2 = (size_t)T * (size_t)B2;

    // float2 channel-plane pointers for this lane pair
    const float2* r0 = (const float2*)ret + tid;
    const float2* r1 = (const float2*)ret + TB2 + tid;
    const float2* x0 = (const float2*)x + tid + B2;          // t = 1
    const float2* x1 = (const float2*)x + TB2 + tid + B2;
    float2* o0 = (float2*)out + tid + B2;                    // t = 1
    float2* o1 = (float2*)out + TB2 + tid + B2;

    // h0 = x[:, 0, :]
    float2 hx = __ldg((const float2*)x + tid);
    float2 hy = __ldg((const float2*)x + TB2 + tid);
    ((float2*)out)[tid] = hx;
    ((float2*)out)[TB2 + tid] = hy;

    // prologue: prefetch buffers for steps 0..PF-1
    float2 fr0[PF], fr1[PF], fx0[PF], fx1[PF];
#pragma unroll
    for (int j = 0; j < PF; ++j) {
        fr0[j] = __ldcs(r0 + (size_t)j * B2);
        fr1[j] = __ldcs(r1 + (size_t)j * B2);
        fx0[j] = __ldcs(x0 + (size_t)j * B2);
        fx1[j] = __ldcs(x1 + (size_t)j * B2);
    }

    // main loop: full groups with unconditional prefetch
    for (int s = 0; s < MAIN_END; s += PF) {
#pragma unroll
        for (int j = 0; j < PF; ++j) {
            float2 rx = fr0[j], ry = fr1[j], xx = fx0[j], xy = fx1[j];
            fr0[j] = __ldcs(r0 + (size_t)(j + PF) * B2);
            fr1[j] = __ldcs(r1 + (size_t)(j + PF) * B2);
            fx0[j] = __ldcs(x0 + (size_t)(j + PF) * B2);
            fx1[j] = __ldcs(x1 + (size_t)(j + PF) * B2);
            ntr_step2(P, hx, hy, rx, ry, xx, xy);
            __stcs(o0 + (size_t)j * B2, hx);
            __stcs(o1 + (size_t)j * B2, hy);
        }
        r0 += (size_t)PF * B2; r1 += (size_t)PF * B2;
        x0 += (size_t)PF * B2; x1 += (size_t)PF * B2;
        o0 += (size_t)PF * B2; o1 += (size_t)PF * B2;
    }

    // tail group A: compile-time-guarded prefetch
#pragma unroll
    for (int j = 0; j < PF; ++j) {
        float2 rx = fr0[j], ry = fr1[j], xx = fx0[j], xy = fx1[j];
        if (j < REM_AFTER_A) {
            fr0[j] = __ldcs(r0 + (size_t)(j + PF) * B2);
            fr1[j] = __ldcs(r1 + (size_t)(j + PF) * B2);
            fx0[j] = __ldcs(x0 + (size_t)(j + PF) * B2);
            fx1[j] = __ldcs(x1 + (size_t)(j + PF) * B2);
        }
        ntr_step2(P, hx, hy, rx, ry, xx, xy);
        __stcs(o0 + (size_t)j * B2, hx);
        __stcs(o1 + (size_t)j * B2, hy);
    }
    o0 += (size_t)PF * B2; o1 += (size_t)PF * B2;

    // tail group B: final steps, no prefetch
#pragma unroll
    for (int j = 0; j < PF; ++j) {
        if (j < REM_AFTER_A) {
            ntr_step2(P, hx, hy, fr0[j], fr1[j], fx0[j], fx1[j]);
            __stcs(o0 + (size_t)j * B2, hx);
            __stcs(o1 + (size_t)j * B2, hy);
        }
    }

    if (write_hT) {
        ((float2*)out)[2 * TB2 + tid] = hx;
        ((float2*)out)[2 * TB2 + B2 + tid] = hy;
    }
}

// ---------------- generic fallback (any T, B) ----------------
__global__ void __launch_bounds__(128)
ntr_rnn_generic(const float* __restrict__ x,
                const float* __restrict__ ret,
                const float* __restrict__ tgt,
                const float* __restrict__ wi,
                const float* __restrict__ wh,
                const float* __restrict__ bh,
                const float* __restrict__ w1,
                const float* __restrict__ w2,
                const float* __restrict__ wr,
                float* __restrict__ out,
                int T, int B, int write_hT)
{
    const int b = blockIdx.x * blockDim.x + threadIdx.x;
    if (b >= B) return;
    const Params P = make_params(tgt, wi, wh, bh, w1, w2, wr);

    const size_t TB = (size_t)T * (size_t)B;
    const float* r0 = ret + b;
    const float* r1 = ret + TB + b;
    const float* x0 = x + b;
    const float* x1 = x + TB + b;
    float* o0 = out + b;
    float* o1 = out + TB + b;

    float hx = __ldg(x0);
    float hy = __ldg(x1);
    o0[0] = hx; o1[0] = hy;

    for (int t = 1; t < T; ++t) {
        size_t offp = (size_t)(t - 1) * B;
        size_t offt = (size_t)t * B;
        float rx = __ldcs(r0 + offp), ry = __ldcs(r1 + offp);
        float xx = __ldcs(x0 + offt), xy = __ldcs(x1 + offt);
        ntr_step(P, hx, hy, rx, ry, xx, xy);
        __stcs(o0 + offt, hx);
        __stcs(o1 + offt, hy);
    }
    if (write_hT) {
        out[2 * TB + b] = hx;
        out[2 * TB + B + b] = hy;
    }
}

extern "C" void kernel_launch(void* const* d_in, const int* in_sizes, int n_in,
                              void* d_out, int out_size)
{
    // 0 input (D,T,B), 1 target, 2 returns (D,T,B), 3 hidden (D,1,B),
    // 4 w_input, 5 w_hidden, 6 b_hidden, 7 w_fc1, 8 w_fc2, 9 w_rotate
    const float* x   = (const float*)d_in[0];
    const float* tgt = (const float*)d_in[1];
    const float* ret = (const float*)d_in[2];
    const float* wi  = (const float*)d_in[4];
    const float* wh  = (const float*)d_in[5];
    const float* bh  = (const float*)d_in[6];
    const float* w1  = (const float*)d_in[7];
    const float* w2  = (const float*)d_in[8];
    const float* wr  = (const float*)d_in[9];
    float* out = (float*)d_out;

    const int D = 2;
    const int B = in_sizes[3] / D;
    const int T = in_sizes[0] / (D * B);
    const int write_hT = (out_size >= D * T * B + D * B) ? 1 : 0;

    constexpr int TS = 512, BS = 16384, PF = 8;
    if (T == TS && B == BS) {
        const int threads = 64;                 // 2 warps/CTA
        const int blocks = (BS / 2) / threads;  // 128 CTAs
        ntr_rnn_ilp2<TS, BS, PF><<<blocks, threads>>>(
            x, ret, tgt, wi, wh, bh, w1, w2, wr, out, write_hT);
    } else {
        const int threads = 128;
        const int blocks = (B + threads - 1) / threads;
        ntr_rnn_generic<<<blocks, threads>>>(
            x, ret, tgt, wi, wh, bh, w1, w2, wr, out, T, B, write_hT);
    }
}